// round 14
// baseline (speedup 1.0000x reference)
#include <cuda_runtime.h>
#include <cuda_bf16.h>
#include <mma.h>

// Problem constants (fixed by the reference)
#define NN    10000
#define MP    10112            // NN padded to 79*128 (no row guards in GEMM)
#define FIN   50
#define K1P   112              // concat K = 50+50 = 100, padded to 7*16
#define HID   512
#define FOUT  121
#define N2P   256              // concat N = 121+121 = 242, padded to 4*64
#define NE    160000

// ---------------- scratch (static device globals: no allocation) ----------------
__device__ int   g_edges[2 * NE];
__device__ int   g_is64;
__device__ int   g_cnt [NN];
__device__ int   g_fill[NN];
__device__ int   g_off [NN + 1];
__device__ int   g_csr [NE];
__device__ __nv_bfloat16 g_acat_hi[MP * K1P];   // [agg1 | x] hi
__device__ __nv_bfloat16 g_acat_lo[MP * K1P];   // [agg1 | x] lo
__device__ __nv_bfloat16 g_w1_hi[K1P * HID];    // [W1l; W1r] hi
__device__ __nv_bfloat16 g_w1_lo[K1P * HID];
__device__ __nv_bfloat16 g_h_hi[MP * HID];      // layer-1 output hi
__device__ __nv_bfloat16 g_h_lo[MP * HID];
__device__ __nv_bfloat16 g_w2_hi[HID * N2P];    // [W2l | W2r] hi
__device__ __nv_bfloat16 g_w2_lo[HID * N2P];
__device__ float g_c2[MP * N2P];                // layer-2 GEMM result (fp32)
__device__ float g_p [NN * FOUT];               // h @ W2_l

// ---------------- helpers ----------------
__device__ __forceinline__ void split_bf16(float v, __nv_bfloat16& hi, __nv_bfloat16& lo) {
    hi = __float2bfloat16(v);
    lo = __float2bfloat16(v - __bfloat162float(hi));
}

// ---------------- edge dtype detection + conversion ----------------
__global__ void k_detect(const int* __restrict__ ei_raw) {
    __shared__ int nz;
    if (threadIdx.x == 0) nz = 0;
    __syncthreads();
    int local = 0;
    for (int i = threadIdx.x; i < 1024; i += blockDim.x)
        if (ei_raw[2 * i + 1] != 0) local = 1;
    if (local) atomicOr(&nz, 1);
    __syncthreads();
    if (threadIdx.x == 0) g_is64 = (nz == 0) ? 1 : 0;
}

__global__ void k_convert(const void* __restrict__ ei_raw) {
    int i = blockIdx.x * blockDim.x + threadIdx.x;
    if (i < 2 * NE) {
        int v;
        if (g_is64) v = (int)((const long long*)ei_raw)[i];
        else        v = ((const int*)ei_raw)[i];
        g_edges[i] = v;
    }
}

// ---------------- CSR build: histogram -> scan -> fill ----------------
__global__ void k_zero2() {
    int i = blockIdx.x * blockDim.x + threadIdx.x;
    if (i < NN) { g_cnt[i] = 0; g_fill[i] = 0; }
}

__global__ void k_hist() {
    int e = blockIdx.x * blockDim.x + threadIdx.x;
    if (e < NE) {
        int d = g_edges[NE + e];
        if ((unsigned)d < NN) atomicAdd(&g_cnt[d], 1);
    }
}

__global__ void k_scan() {
    __shared__ int tmp[1024];
    const int t = threadIdx.x;
    const int idx0 = t * 10;
    int local[10];
    int part = 0;
#pragma unroll
    for (int j = 0; j < 10; j++) {
        int idx = idx0 + j;
        int c = (idx < NN) ? g_cnt[idx] : 0;
        local[j] = c;
        part += c;
    }
    tmp[t] = part;
    __syncthreads();
    for (int off = 1; off < 1024; off <<= 1) {
        int v = (t >= off) ? tmp[t - off] : 0;
        __syncthreads();
        tmp[t] += v;
        __syncthreads();
    }
    int excl = tmp[t] - part;
#pragma unroll
    for (int j = 0; j < 10; j++) {
        int idx = idx0 + j;
        if (idx < NN) g_off[idx] = excl;
        excl += local[j];
    }
    if (t == 1023) g_off[NN] = tmp[1023];
}

__global__ void k_fill() {
    int e = blockIdx.x * blockDim.x + threadIdx.x;
    if (e < NE) {
        int s = g_edges[e];
        int d = g_edges[NE + e];
        if ((unsigned)s < NN && (unsigned)d < NN) {
            int pos = g_off[d] + atomicAdd(&g_fill[d], 1);
            g_csr[pos] = s;
        }
    }
}

// ---------------- zero a bf16 buffer (as uint32 words; sizes are even) ----------------
__global__ void k_z32(unsigned int* __restrict__ p, int n32) {
    int i = blockIdx.x * blockDim.x + threadIdx.x;
    if (i < n32) p[i] = 0u;
}

// ---------------- gather-mean of x into Acat cols [0,50) ----------------
__global__ void k_agg1(const float* __restrict__ x) {
    int gid  = blockIdx.x * blockDim.x + threadIdx.x;
    int w    = gid >> 5;
    int lane = gid & 31;
    if (w >= NN) return;
    int b = g_off[w], e = g_off[w + 1];
    float s0 = 0.0f, s1 = 0.0f;
    for (int i = b; i < e; i++) {
        int src = g_csr[i];
        const float* row = x + (long)src * FIN;
        s0 += row[lane];
        if (lane + 32 < FIN) s1 += row[lane + 32];
    }
    float inv = 1.0f / fmaxf((float)(e - b), 1.0f);
    __nv_bfloat16 hi, lo;
    long base = (long)w * K1P;
    split_bf16(s0 * inv, hi, lo);
    g_acat_hi[base + lane] = hi;
    g_acat_lo[base + lane] = lo;
    if (lane + 32 < FIN) {
        split_bf16(s1 * inv, hi, lo);
        g_acat_hi[base + lane + 32] = hi;
        g_acat_lo[base + lane + 32] = lo;
    }
}

// ---------------- x into Acat cols [50,100) ----------------
__global__ void k_convx(const float* __restrict__ x) {
    int i = blockIdx.x * blockDim.x + threadIdx.x;
    if (i < NN * FIN) {
        int row = i / FIN, c = i - row * FIN;
        __nv_bfloat16 hi, lo;
        split_bf16(x[i], hi, lo);
        long o = (long)row * K1P + FIN + c;
        g_acat_hi[o] = hi;
        g_acat_lo[o] = lo;
    }
}

// ---------------- W1cat = [W1l; W1r] padded to 112 rows ----------------
__global__ void k_convW1(const float* __restrict__ W1l, const float* __restrict__ W1r) {
    int i = blockIdx.x * blockDim.x + threadIdx.x;
    if (i < K1P * HID) {
        int row = i / HID, c = i - row * HID;
        float v = 0.0f;
        if (row < FIN)            v = W1l[row * HID + c];
        else if (row < 2 * FIN)   v = W1r[(row - FIN) * HID + c];
        __nv_bfloat16 hi, lo;
        split_bf16(v, hi, lo);
        g_w1_hi[i] = hi;
        g_w1_lo[i] = lo;
    }
}

// ---------------- W2cat = [W2l | W2r] padded to 256 cols ----------------
__global__ void k_convW2(const float* __restrict__ W2l, const float* __restrict__ W2r) {
    int i = blockIdx.x * blockDim.x + threadIdx.x;
    if (i < HID * N2P) {
        int k = i / N2P, c = i - k * N2P;
        float v = 0.0f;
        if (c < FOUT)            v = W2l[k * FOUT + c];
        else if (c < 2 * FOUT)   v = W2r[k * FOUT + (c - FOUT)];
        __nv_bfloat16 hi, lo;
        split_bf16(v, hi, lo);
        g_w2_hi[i] = hi;
        g_w2_lo[i] = lo;
    }
}

// ---------------- split-precision bf16 wmma GEMM ----------------
// C = Ahi@Bhi + Ahi@Blo + Alo@Bhi (fp32 accum). Tile 128x64, 8 warps, each 32x32.
// EPI==0: bias + relu, split result to bf16 hi/lo (layer 1 -> h).
// EPI==1: plain fp32 store (layer 2 -> g_c2 scratch).
template <int EPI>
__global__ __launch_bounds__(256)
void wgemm(const __nv_bfloat16* __restrict__ Ah, const __nv_bfloat16* __restrict__ Al, int lda,
           const __nv_bfloat16* __restrict__ Bh, const __nv_bfloat16* __restrict__ Bl, int ldb,
           int ksteps,
           const float* __restrict__ bias,
           __nv_bfloat16* __restrict__ Oh, __nv_bfloat16* __restrict__ Ol, int ldo,
           float* __restrict__ Cf, int ldc)
{
    using namespace nvcuda;
    __shared__ __align__(16) union SU {
        struct {
            __nv_bfloat16 Ah[128 * 16];
            __nv_bfloat16 Al[128 * 16];
            __nv_bfloat16 Bh[16 * 64];
            __nv_bfloat16 Bl[16 * 64];
        } ld;
        float stage[8][32 * 36];
    } sm;

    const int tid  = threadIdx.x;
    const int wid  = tid >> 5;
    const int lane = tid & 31;
    const int m0 = blockIdx.y * 128;
    const int n0 = blockIdx.x * 64;
    const int wm = wid >> 1;       // 0..3: warp row (32 rows each)
    const int wn = wid & 1;        // 0..1: warp col (32 cols each)

    wmma::fragment<wmma::accumulator, 16, 16, 16, float> acc[2][2];
#pragma unroll
    for (int i = 0; i < 2; i++)
#pragma unroll
        for (int j = 0; j < 2; j++) wmma::fill_fragment(acc[i][j], 0.0f);

    const int ar  = tid >> 1;          // A row 0..127
    const int ah2 = tid & 1;           // 8-element half
    const int bt  = tid & 127;
    const int br  = bt >> 3;           // B row 0..15
    const int bs  = bt & 7;            // 8-element segment

    for (int kt = 0; kt < ksteps; kt++) {
        const int k0 = kt * 16;
        // A tiles: one uint4 (8 bf16) per thread per array
        ((uint4*)sm.ld.Ah)[tid] = *(const uint4*)(Ah + (long)(m0 + ar) * lda + k0 + ah2 * 8);
        ((uint4*)sm.ld.Al)[tid] = *(const uint4*)(Al + (long)(m0 + ar) * lda + k0 + ah2 * 8);
        // B tiles: threads 0..127 load hi, 128..255 load lo
        {
            const __nv_bfloat16* bsrc = (tid < 128) ? Bh : Bl;
            __nv_bfloat16* bdst = (tid < 128) ? sm.ld.Bh : sm.ld.Bl;
            ((uint4*)bdst)[bt] = *(const uint4*)(bsrc + (long)(k0 + br) * ldb + n0 + bs * 8);
        }
        __syncthreads();

        wmma::fragment<wmma::matrix_a, 16, 16, 16, __nv_bfloat16, wmma::row_major> fah[2], fal[2];
        wmma::fragment<wmma::matrix_b, 16, 16, 16, __nv_bfloat16, wmma::row_major> fbh[2], fbl[2];
#pragma unroll
        for (int i = 0; i < 2; i++) {
            wmma::load_matrix_sync(fah[i], sm.ld.Ah + (wm * 32 + i * 16) * 16, 16);
            wmma::load_matrix_sync(fal[i], sm.ld.Al + (wm * 32 + i * 16) * 16, 16);
        }
#pragma unroll
        for (int j = 0; j < 2; j++) {
            wmma::load_matrix_sync(fbh[j], sm.ld.Bh + wn * 32 + j * 16, 64);
            wmma::load_matrix_sync(fbl[j], sm.ld.Bl + wn * 32 + j * 16, 64);
        }
#pragma unroll
        for (int i = 0; i < 2; i++)
#pragma unroll
            for (int j = 0; j < 2; j++) {
                wmma::mma_sync(acc[i][j], fah[i], fbh[j], acc[i][j]);
                wmma::mma_sync(acc[i][j], fah[i], fbl[j], acc[i][j]);
                wmma::mma_sync(acc[i][j], fal[i], fbh[j], acc[i][j]);
            }
        __syncthreads();
    }

    if (EPI == 1) {
        // direct fp32 store (buffers padded: no guards)
#pragma unroll
        for (int i = 0; i < 2; i++)
#pragma unroll
            for (int j = 0; j < 2; j++)
                wmma::store_matrix_sync(Cf + (long)(m0 + wm * 32 + i * 16) * ldc
                                           + n0 + wn * 32 + j * 16,
                                        acc[i][j], ldc, wmma::mem_row_major);
    } else {
        // stage per warp, fuse bias+relu, split to bf16 hi/lo
        float* st = sm.stage[wid];
#pragma unroll
        for (int i = 0; i < 2; i++)
#pragma unroll
            for (int j = 0; j < 2; j++)
                wmma::store_matrix_sync(st + i * 16 * 36 + j * 16, acc[i][j], 36,
                                        wmma::mem_row_major);
        __syncwarp();
        const int gn = n0 + wn * 32 + lane;
        const float bv = bias[gn];
#pragma unroll 4
        for (int r = 0; r < 32; r++) {
            float v = st[r * 36 + lane] + bv;
            v = fmaxf(v, 0.0f);
            __nv_bfloat16 hi, lo;
            split_bf16(v, hi, lo);
            long off = (long)(m0 + wm * 32 + r) * ldo + gn;
            Oh[off] = hi;
            Ol[off] = lo;
        }
    }
}

// ---------------- split layer-2 result: p and out(+b2) ----------------
__global__ void k_split(float* __restrict__ out, const float* __restrict__ b2) {
    int i = blockIdx.x * blockDim.x + threadIdx.x;
    if (i < NN * 2 * FOUT) {
        int row = i / (2 * FOUT);
        int c   = i - row * (2 * FOUT);
        float v = g_c2[(long)row * N2P + c];
        if (c < FOUT) g_p[(long)row * FOUT + c] = v;
        else          out[(long)row * FOUT + (c - FOUT)] = v + b2[c - FOUT];
    }
}

// ---------------- out += gather-mean of p ----------------
__global__ void k_agg2(float* __restrict__ out) {
    int gid  = blockIdx.x * blockDim.x + threadIdx.x;
    int w    = gid >> 5;
    int lane = gid & 31;
    if (w >= NN) return;
    int b = g_off[w], e = g_off[w + 1];
    float s0 = 0.0f, s1 = 0.0f, s2 = 0.0f, s3 = 0.0f;
    for (int i = b; i < e; i++) {
        int src = g_csr[i];
        const float* row = g_p + (long)src * FOUT;
        s0 += row[lane];
        s1 += row[lane + 32];
        s2 += row[lane + 64];
        if (lane + 96 < FOUT) s3 += row[lane + 96];
    }
    float inv = 1.0f / fmaxf((float)(e - b), 1.0f);
    float* orow = out + (long)w * FOUT;
    orow[lane]      += s0 * inv;
    orow[lane + 32] += s1 * inv;
    orow[lane + 64] += s2 * inv;
    if (lane + 96 < FOUT) orow[lane + 96] += s3 * inv;
}

// ---------------- launch ----------------
extern "C" void kernel_launch(void* const* d_in, const int* in_sizes, int n_in,
                              void* d_out, int out_size)
{
    const float* x   = (const float*)d_in[0];
    const void*  ei  = d_in[1];
    const float* W1l = (const float*)d_in[2];
    const float* W1r = (const float*)d_in[3];
    const float* b1  = (const float*)d_in[4];
    const float* W2l = (const float*)d_in[5];
    const float* W2r = (const float*)d_in[6];
    const float* b2  = (const float*)d_in[7];
    float*       out = (float*)d_out;

    void *p_ahi, *p_alo, *p_w1h, *p_w1l, *p_hhi, *p_hlo, *p_w2h, *p_w2l, *p_c2;
    cudaGetSymbolAddress(&p_ahi, g_acat_hi);
    cudaGetSymbolAddress(&p_alo, g_acat_lo);
    cudaGetSymbolAddress(&p_w1h, g_w1_hi);
    cudaGetSymbolAddress(&p_w1l, g_w1_lo);
    cudaGetSymbolAddress(&p_hhi, g_h_hi);
    cudaGetSymbolAddress(&p_hlo, g_h_lo);
    cudaGetSymbolAddress(&p_w2h, g_w2_hi);
    cudaGetSymbolAddress(&p_w2l, g_w2_lo);
    cudaGetSymbolAddress(&p_c2,  g_c2);

    // edge dtype detect + convert
    k_detect<<<1, 256>>>((const int*)ei);
    k_convert<<<(2 * NE + 255) / 256, 256>>>(ei);

    // CSR by destination
    k_zero2<<<(NN + 255) / 256, 256>>>();
    k_hist<<<(NE + 255) / 256, 256>>>();
    k_scan<<<1, 1024>>>();
    k_fill<<<(NE + 255) / 256, 256>>>();

    // zero Acat (covers K-pad cols and M-pad rows)
    {
        int n32 = MP * K1P / 2;
        k_z32<<<(n32 + 255) / 256, 256>>>((unsigned int*)p_ahi, n32);
        k_z32<<<(n32 + 255) / 256, 256>>>((unsigned int*)p_alo, n32);
    }

    // operand prep
    k_agg1<<<(NN * 32 + 255) / 256, 256>>>(x);
    k_convx<<<(NN * FIN + 255) / 256, 256>>>(x);
    k_convW1<<<(K1P * HID + 255) / 256, 256>>>(W1l, W1r);
    k_convW2<<<(HID * N2P + 255) / 256, 256>>>(W2l, W2r);

    // layer 1: h(hi/lo) = relu([agg1|x] @ [W1l;W1r] + b1)   (tensor, split bf16)
    {
        dim3 grid(HID / 64, MP / 128);
        wgemm<0><<<grid, 256>>>((const __nv_bfloat16*)p_ahi, (const __nv_bfloat16*)p_alo, K1P,
                                (const __nv_bfloat16*)p_w1h, (const __nv_bfloat16*)p_w1l, HID,
                                K1P / 16, b1,
                                (__nv_bfloat16*)p_hhi, (__nv_bfloat16*)p_hlo, HID,
                                nullptr, 0);
    }

    // layer 2: c2 = h @ [W2l|W2r]   (tensor, split bf16)
    {
        dim3 grid(N2P / 64, MP / 128);
        wgemm<1><<<grid, 256>>>((const __nv_bfloat16*)p_hhi, (const __nv_bfloat16*)p_hlo, HID,
                                (const __nv_bfloat16*)p_w2h, (const __nv_bfloat16*)p_w2l, N2P,
                                HID / 16, nullptr,
                                nullptr, nullptr, 0,
                                (float*)p_c2, N2P);
    }

    // split c2 -> p, out(+b2); then out += gather-mean(p)
    k_split<<<(NN * 2 * FOUT + 255) / 256, 256>>>(out, b2);
    k_agg2<<<(NN * 32 + 255) / 256, 256>>>(out);
}

// round 15
// speedup vs baseline: 1.6738x; 1.6738x over previous
#include <cuda_runtime.h>

// Problem constants (fixed by the reference)
#define NN   10000
#define FIN  50
#define HID  512
#define FOUT 121
#define NE   160000

// ---------------- scratch (static device globals: no allocation) ----------------
__device__ int   g_edges[2 * NE];
__device__ int   g_is64;
__device__ int   g_cnt [NN];
__device__ int   g_fill[NN];
__device__ int   g_off [NN + 1];
__device__ int   g_csr [NE];
__device__ float g_agg1[NN * FIN];
__device__ float g_h   [NN * HID];
__device__ float g_p   [NN * FOUT];

// ---------------- edge dtype detection + conversion ----------------
__global__ void k_detect(const int* __restrict__ ei_raw) {
    __shared__ int nz;
    if (threadIdx.x == 0) nz = 0;
    __syncthreads();
    int local = 0;
    for (int i = threadIdx.x; i < 1024; i += blockDim.x)
        if (ei_raw[2 * i + 1] != 0) local = 1;
    if (local) atomicOr(&nz, 1);
    __syncthreads();
    if (threadIdx.x == 0) g_is64 = (nz == 0) ? 1 : 0;
}

__global__ void k_convert(const void* __restrict__ ei_raw) {
    int i = blockIdx.x * blockDim.x + threadIdx.x;
    if (i < 2 * NE) {
        int v;
        if (g_is64) v = (int)((const long long*)ei_raw)[i];
        else        v = ((const int*)ei_raw)[i];
        g_edges[i] = v;
    }
}

// ---------------- CSR build: histogram -> scan -> fill ----------------
__global__ void k_zero2() {
    int i = blockIdx.x * blockDim.x + threadIdx.x;
    if (i < NN) { g_cnt[i] = 0; g_fill[i] = 0; }
}

__global__ void k_hist() {
    int e = blockIdx.x * blockDim.x + threadIdx.x;
    if (e < NE) {
        int d = g_edges[NE + e];
        if ((unsigned)d < NN) atomicAdd(&g_cnt[d], 1);
    }
}

__global__ void k_scan() {
    __shared__ int tmp[1024];
    const int t = threadIdx.x;
    const int idx0 = t * 10;
    int local[10];
    int part = 0;
#pragma unroll
    for (int j = 0; j < 10; j++) {
        int idx = idx0 + j;
        int c = (idx < NN) ? g_cnt[idx] : 0;
        local[j] = c;
        part += c;
    }
    tmp[t] = part;
    __syncthreads();
    for (int off = 1; off < 1024; off <<= 1) {
        int v = (t >= off) ? tmp[t - off] : 0;
        __syncthreads();
        tmp[t] += v;
        __syncthreads();
    }
    int excl = tmp[t] - part;
#pragma unroll
    for (int j = 0; j < 10; j++) {
        int idx = idx0 + j;
        if (idx < NN) g_off[idx] = excl;
        excl += local[j];
    }
    if (t == 1023) g_off[NN] = tmp[1023];
}

__global__ void k_fill() {
    int e = blockIdx.x * blockDim.x + threadIdx.x;
    if (e < NE) {
        int s = g_edges[e];
        int d = g_edges[NE + e];
        if ((unsigned)s < NN && (unsigned)d < NN) {
            int pos = g_off[d] + atomicAdd(&g_fill[d], 1);
            g_csr[pos] = s;
        }
    }
}

// ---------------- gather aggregations (no atomics) ----------------
__global__ void k_agg1(const float* __restrict__ x) {
    int gid  = blockIdx.x * blockDim.x + threadIdx.x;
    int w    = gid >> 5;
    int lane = gid & 31;
    if (w >= NN) return;
    int b = g_off[w], e = g_off[w + 1];
    float s0 = 0.0f, s1 = 0.0f;
    for (int i = b; i < e; i++) {
        int src = g_csr[i];
        const float* row = x + (long)src * FIN;
        s0 += row[lane];
        if (lane + 32 < FIN) s1 += row[lane + 32];
    }
    float inv = 1.0f / fmaxf((float)(e - b), 1.0f);
    g_agg1[w * FIN + lane] = s0 * inv;
    if (lane + 32 < FIN) g_agg1[w * FIN + lane + 32] = s1 * inv;
}

__global__ void k_agg2(float* __restrict__ out) {
    int gid  = blockIdx.x * blockDim.x + threadIdx.x;
    int w    = gid >> 5;
    int lane = gid & 31;
    if (w >= NN) return;
    int b = g_off[w], e = g_off[w + 1];
    float s0 = 0.0f, s1 = 0.0f, s2 = 0.0f, s3 = 0.0f;
    for (int i = b; i < e; i++) {
        int src = g_csr[i];
        const float* row = g_p + (long)src * FOUT;
        s0 += row[lane];
        s1 += row[lane + 32];
        s2 += row[lane + 64];
        if (lane + 96 < FOUT) s3 += row[lane + 96];
    }
    float inv = 1.0f / fmaxf((float)(e - b), 1.0f);
    float* orow = out + (long)w * FOUT;
    orow[lane]      += s0 * inv;
    orow[lane + 32] += s1 * inv;
    orow[lane + 64] += s2 * inv;
    if (lane + 96 < FOUT) orow[lane + 96] += s3 * inv;
}

// ---------------- fp32 tiled GEMM, dual-A (layer 1) — unchanged from R12 ----------------
__global__ __launch_bounds__(256)
void gemm1_k(const float* __restrict__ A1, const float* __restrict__ W1,
             const float* __restrict__ A2, const float* __restrict__ W2,
             const float* __restrict__ bias, float* __restrict__ C,
             int M, int N, int K)
{
    constexpr int BM = 64, BN = 64, BK = 16, TM = 4, TN = 4;
    __shared__ float sA1[BK][BM];
    __shared__ float sW1[BK][BN];
    __shared__ float sA2[BK][BM];
    __shared__ float sW2[BK][BN];

    const int tid = threadIdx.x;
    const int tx = tid % 16;
    const int ty = tid / 16;
    const int m0 = blockIdx.y * BM;
    const int n0 = blockIdx.x * BN;

    float acc[TM][TN];
#pragma unroll
    for (int i = 0; i < TM; i++)
#pragma unroll
        for (int j = 0; j < TN; j++) acc[i][j] = 0.0f;

    const int arow = tid / 4;
    const int ac0  = (tid % 4) * 4;
    const int wcol = tid % 64;
    const int wr0  = tid / 64;

    for (int k0 = 0; k0 < K; k0 += BK) {
#pragma unroll
        for (int i = 0; i < 4; i++) {
            int k = k0 + ac0 + i;
            int m = m0 + arow;
            float v1 = 0.0f, v2 = 0.0f;
            if (m < M && k < K) {
                v1 = A1[(long)m * K + k];
                v2 = A2[(long)m * K + k];
            }
            sA1[ac0 + i][arow] = v1;
            sA2[ac0 + i][arow] = v2;
        }
#pragma unroll
        for (int it = 0; it < 4; it++) {
            int kr = wr0 + it * 4;
            int k = k0 + kr;
            int n = n0 + wcol;
            float v1 = 0.0f, v2 = 0.0f;
            if (k < K && n < N) {
                v1 = W1[(long)k * N + n];
                v2 = W2[(long)k * N + n];
            }
            sW1[kr][wcol] = v1;
            sW2[kr][wcol] = v2;
        }
        __syncthreads();

#pragma unroll
        for (int kk = 0; kk < BK; kk++) {
            float a1[TM], w1[TN], a2[TM], w2[TN];
#pragma unroll
            for (int i = 0; i < TM; i++) {
                a1[i] = sA1[kk][ty * TM + i];
                a2[i] = sA2[kk][ty * TM + i];
            }
#pragma unroll
            for (int j = 0; j < TN; j++) {
                w1[j] = sW1[kk][tx * TN + j];
                w2[j] = sW2[kk][tx * TN + j];
            }
#pragma unroll
            for (int i = 0; i < TM; i++)
#pragma unroll
                for (int j = 0; j < TN; j++) {
                    acc[i][j] += a1[i] * w1[j];
                    acc[i][j] += a2[i] * w2[j];
                }
        }
        __syncthreads();
    }

#pragma unroll
    for (int i = 0; i < TM; i++) {
        int m = m0 + ty * TM + i;
        if (m >= M) continue;
#pragma unroll
        for (int j = 0; j < TN; j++) {
            int n = n0 + tx * TN + j;
            if (n >= N) continue;
            float v = acc[i][j] + bias[n];
            C[(long)m * N + n] = fmaxf(v, 0.0f);
        }
    }
}

// ---------------- fp32 dual-B GEMM (layer 2), double-buffered pipeline ----------------
// C1 = A@Wa, C2 = A@Wb + bias. K assumed multiple of BK (K=512).
// Prefetch next k-tile's GMEM into registers during compute; one sync/iter.
__global__ __launch_bounds__(256)
void gemm2_k(const float* __restrict__ A,
             const float* __restrict__ Wa, const float* __restrict__ Wb,
             const float* __restrict__ bias,
             float* __restrict__ C1, float* __restrict__ C2,
             int M, int N, int K)
{
    constexpr int BM = 64, BN = 64, BK = 16, TM = 4, TN = 4;
    __shared__ float sA [2][BK][BM];
    __shared__ float sWa[2][BK][BN];
    __shared__ float sWb[2][BK][BN];

    const int tid = threadIdx.x;
    const int tx = tid % 16;
    const int ty = tid / 16;
    const int m0 = blockIdx.y * BM;
    const int n0 = blockIdx.x * BN;

    float acc1[TM][TN], acc2[TM][TN];
#pragma unroll
    for (int i = 0; i < TM; i++)
#pragma unroll
        for (int j = 0; j < TN; j++) { acc1[i][j] = 0.0f; acc2[i][j] = 0.0f; }

    const int arow = tid / 4;            // 0..63
    const int ac0  = (tid % 4) * 4;      // 0,4,8,12 (float4-aligned, K=512)
    const int am   = m0 + arow;
    const bool aok = (am < M);
    const int wcol = tid % 64;
    const int wr0  = tid / 64;
    const int wn   = n0 + wcol;
    const bool wok = (wn < N);
    const int nk = K / BK;

    // preload tile 0 into buffer 0
    {
        float4 va = make_float4(0.f, 0.f, 0.f, 0.f);
        if (aok) va = *(const float4*)(A + (long)am * K + ac0);
        sA[0][ac0 + 0][arow] = va.x;
        sA[0][ac0 + 1][arow] = va.y;
        sA[0][ac0 + 2][arow] = va.z;
        sA[0][ac0 + 3][arow] = va.w;
#pragma unroll
        for (int it = 0; it < 4; it++) {
            int kr = wr0 + it * 4;
            float va2 = 0.f, vb2 = 0.f;
            if (wok) {
                va2 = Wa[(long)kr * N + wn];
                vb2 = Wb[(long)kr * N + wn];
            }
            sWa[0][kr][wcol] = va2;
            sWb[0][kr][wcol] = vb2;
        }
    }
    __syncthreads();

    int buf = 0;
    for (int kt = 0; kt < nk; kt++) {
        // prefetch next tile into registers
        float4 pa = make_float4(0.f, 0.f, 0.f, 0.f);
        float pwa[4], pwb[4];
        const bool more = (kt + 1 < nk);
        if (more) {
            const int k0n = (kt + 1) * BK;
            if (aok) pa = *(const float4*)(A + (long)am * K + k0n + ac0);
#pragma unroll
            for (int it = 0; it < 4; it++) {
                int kr = wr0 + it * 4;
                float va2 = 0.f, vb2 = 0.f;
                if (wok) {
                    va2 = Wa[(long)(k0n + kr) * N + wn];
                    vb2 = Wb[(long)(k0n + kr) * N + wn];
                }
                pwa[it] = va2;
                pwb[it] = vb2;
            }
        }

        // compute from current buffer
#pragma unroll
        for (int kk = 0; kk < BK; kk++) {
            float a[TM], wa[TN], wb[TN];
#pragma unroll
            for (int i = 0; i < TM; i++) a[i] = sA[buf][kk][ty * TM + i];
#pragma unroll
            for (int j = 0; j < TN; j++) {
                wa[j] = sWa[buf][kk][tx * TN + j];
                wb[j] = sWb[buf][kk][tx * TN + j];
            }
#pragma unroll
            for (int i = 0; i < TM; i++)
#pragma unroll
                for (int j = 0; j < TN; j++) {
                    acc1[i][j] += a[i] * wa[j];
                    acc2[i][j] += a[i] * wb[j];
                }
        }

        // store prefetched tile into the other buffer
        if (more) {
            const int nb = buf ^ 1;
            sA[nb][ac0 + 0][arow] = pa.x;
            sA[nb][ac0 + 1][arow] = pa.y;
            sA[nb][ac0 + 2][arow] = pa.z;
            sA[nb][ac0 + 3][arow] = pa.w;
#pragma unroll
            for (int it = 0; it < 4; it++) {
                int kr = wr0 + it * 4;
                sWa[nb][kr][wcol] = pwa[it];
                sWb[nb][kr][wcol] = pwb[it];
            }
        }
        __syncthreads();
        buf ^= 1;
    }

#pragma unroll
    for (int i = 0; i < TM; i++) {
        int m = m0 + ty * TM + i;
        if (m >= M) continue;
#pragma unroll
        for (int j = 0; j < TN; j++) {
            int n = n0 + tx * TN + j;
            if (n >= N) continue;
            C1[(long)m * N + n] = acc1[i][j];
            C2[(long)m * N + n] = acc2[i][j] + bias[n];
        }
    }
}

// ---------------- launch ----------------
extern "C" void kernel_launch(void* const* d_in, const int* in_sizes, int n_in,
                              void* d_out, int out_size)
{
    const float* x   = (const float*)d_in[0];
    const void*  ei  = d_in[1];
    const float* W1l = (const float*)d_in[2];
    const float* W1r = (const float*)d_in[3];
    const float* b1  = (const float*)d_in[4];
    const float* W2l = (const float*)d_in[5];
    const float* W2r = (const float*)d_in[6];
    const float* b2  = (const float*)d_in[7];
    float*       out = (float*)d_out;

    float *p_agg1, *p_h, *p_p;
    cudaGetSymbolAddress((void**)&p_agg1, g_agg1);
    cudaGetSymbolAddress((void**)&p_h,    g_h);
    cudaGetSymbolAddress((void**)&p_p,    g_p);

    // edge dtype detect + convert to int32
    k_detect<<<1, 256>>>((const int*)ei);
    k_convert<<<(2 * NE + 255) / 256, 256>>>(ei);

    // CSR by destination: histogram -> exclusive scan -> bucket fill
    k_zero2<<<(NN + 255) / 256, 256>>>();
    k_hist<<<(NE + 255) / 256, 256>>>();
    k_scan<<<1, 1024>>>();
    k_fill<<<(NE + 255) / 256, 256>>>();

    // layer 1: gather-mean of x (warp per dst), fused dual-A GEMM + bias + relu
    k_agg1<<<(NN * 32 + 255) / 256, 256>>>(x);
    {
        dim3 grid((HID + 63) / 64, (NN + 63) / 64);
        gemm1_k<<<grid, 256>>>(p_agg1, W1l, x, W1r, b1, p_h, NN, HID, FIN);
    }

    // layer 2: fused dual-B GEMM (double-buffered), then out += gather-mean(p)
    {
        dim3 grid((FOUT + 63) / 64, (NN + 63) / 64);
        gemm2_k<<<grid, 256>>>(p_h, W2l, W2r, b2, p_p, out, NN, FOUT, HID);
        k_agg2<<<(NN * 32 + 255) / 256, 256>>>(out);
    }
}